// round 14
// baseline (speedup 1.0000x reference)
#include <cuda_runtime.h>

typedef unsigned long long ull;

#define TLEN 512
#define BSZ  128
#define MDIM 31
#define HSZ  512
#define ESZ  256
#define SSZ  128
#define G3   1536
#define TB   65536
#define NSTEP 511
#define HS_SLICE 65536
#define NB4B  8176
#define LOG2PI 1.8378770664093453f

#define SW_ULL    8192          // [512 k][4 up][4 slots(3 used)] = 64KB
#define SPART_ULL 6144          // [16 kq][3 g][4 r][4 up][8 iq]  = 48KB
#define K3_SMEM_BYTES ((SW_ULL + SPART_ULL) * 8)   // 114688 (x2/SM = 229376)

// ---------------- scratch ----------------
__device__ float g_phi[TB * ESZ];                    // [t*128+i][e]
__device__ float g_xg[(size_t)TB * G3];              // [t][col(1536)][i(128)]
__device__ float g_hs[(size_t)TLEN * BSZ * HSZ];     // [t][i][k]
__device__ float g_hsT[(size_t)TLEN * BSZ * HSZ];    // [t][k][i]
__device__ float g_he[(size_t)TB * SSZ];
__device__ float g_partial[NB4B];
__device__ unsigned g_sub[4 * 8 * 32];               // [bg][sub(8)] counters, 128B apart

// ---------------- helpers ----------------
__device__ __forceinline__ ull pk2(float x, float y) {
    ull r; asm("mov.b64 %0, {%1, %2};" : "=l"(r) : "f"(x), "f"(y)); return r;
}
__device__ __forceinline__ ull fma2(ull a, ull b, ull c) {
    ull d; asm("fma.rn.f32x2 %0, %1, %2, %3;" : "=l"(d) : "l"(a), "l"(b), "l"(c)); return d;
}
__device__ __forceinline__ ull add2(ull a, ull b) {
    ull d; asm("add.rn.f32x2 %0, %1, %2;" : "=l"(d) : "l"(a), "l"(b)); return d;
}
__device__ __forceinline__ float2 up2(ull v) {
    float2 f; asm("mov.b64 {%0, %1}, %2;" : "=f"(f.x), "=f"(f.y) : "l"(v)); return f;
}
__device__ __forceinline__ float sigm(float v) { return 1.f / (1.f + __expf(-v)); }
__device__ __forceinline__ void pf_l2(const void* p) {
    asm volatile("prefetch.global.L2 [%0];" :: "l"(p));
}

// ---------------- K0: init ----------------
__global__ void k0_init() {
    int idx = blockIdx.x * 256 + threadIdx.x;
    if (idx < HS_SLICE) { g_hsT[idx] = 0.f; g_hs[idx] = 0.f; }
    if (idx < 4 * 8 * 32) g_sub[idx] = 0u;
}

// ---------------- K1: phi = relu(x @ W_embed^T + b) ----------------
__global__ void __launch_bounds__(256) k1_embed(const float* __restrict__ x,
                                                const float* __restrict__ W_embed,
                                                const float* __restrict__ b_embed) {
    __shared__ float sx[64][32];
    const int tid = threadIdx.x;
    const int row0 = blockIdx.x * 64;
    for (int idx = tid; idx < 64 * MDIM; idx += 256) {
        int r = idx / MDIM, c = idx - r * MDIM;
        sx[r][c] = x[(size_t)(row0 + r) * MDIM + c];
    }
    float wreg[MDIM];
    const float* wp = W_embed + tid * MDIM;
#pragma unroll
    for (int k = 0; k < MDIM; k++) wreg[k] = __ldg(wp + k);
    float bb = __ldg(b_embed + tid);
    __syncthreads();
#pragma unroll 4
    for (int r = 0; r < 64; r++) {
        float acc = bb;
#pragma unroll
        for (int k = 0; k < MDIM; k++) acc += sx[r][k] * wreg[k];
        g_phi[(size_t)(row0 + r) * ESZ + tid] = fmaxf(acc, 0.f);
    }
}

// ---------------- K2: xgT[t][col][i] (v11 form) ----------------
__global__ void __launch_bounds__(256) k2_gatesT(const float* __restrict__ W_ih,
                                                 const float* __restrict__ b_ih) {
    __shared__ float As[16][128];
    __shared__ float Bs[16][128];
    const int tid = threadIdx.x;
    const int t = blockIdx.z;
    const int m0 = blockIdx.x * 128;
    const float* A = W_ih;
    const float* B = g_phi + (size_t)t * BSZ * ESZ;
    float*       C = g_xg  + (size_t)t * G3 * BSZ;
    const int lr = tid >> 1, ls = (tid & 1) * 8;
    const int tx = tid & 15, ty = tid >> 4;
    ull acc[8][4];
#pragma unroll
    for (int i = 0; i < 8; i++)
#pragma unroll
        for (int j = 0; j < 4; j++) acc[i][j] = 0ull;

    const float* Ap = A + (size_t)(m0 + lr) * ESZ + ls;
    const float* Bp = B + (size_t)lr * ESZ + ls;

    for (int kt = 0; kt < ESZ; kt += 16) {
        float4 a0 = *(const float4*)(Ap + kt);
        float4 a1 = *(const float4*)(Ap + kt + 4);
        float4 b0 = *(const float4*)(Bp + kt);
        float4 b1 = *(const float4*)(Bp + kt + 4);
        __syncthreads();
        As[ls + 0][lr] = a0.x; As[ls + 1][lr] = a0.y; As[ls + 2][lr] = a0.z; As[ls + 3][lr] = a0.w;
        As[ls + 4][lr] = a1.x; As[ls + 5][lr] = a1.y; As[ls + 6][lr] = a1.z; As[ls + 7][lr] = a1.w;
        Bs[ls + 0][lr] = b0.x; Bs[ls + 1][lr] = b0.y; Bs[ls + 2][lr] = b0.z; Bs[ls + 3][lr] = b0.w;
        Bs[ls + 4][lr] = b1.x; Bs[ls + 5][lr] = b1.y; Bs[ls + 6][lr] = b1.z; Bs[ls + 7][lr] = b1.w;
        __syncthreads();
#pragma unroll
        for (int k = 0; k < 16; k++) {
            float4 av0 = *(const float4*)&As[k][ty * 8];
            float4 av1 = *(const float4*)&As[k][ty * 8 + 4];
            float4 bv0 = *(const float4*)&Bs[k][tx * 8];
            float4 bv1 = *(const float4*)&Bs[k][tx * 8 + 4];
            ull bp0 = pk2(bv0.x, bv0.y), bp1 = pk2(bv0.z, bv0.w);
            ull bp2 = pk2(bv1.x, bv1.y), bp3 = pk2(bv1.z, bv1.w);
            float aa[8] = {av0.x, av0.y, av0.z, av0.w, av1.x, av1.y, av1.z, av1.w};
#pragma unroll
            for (int i = 0; i < 8; i++) {
                ull ap = pk2(aa[i], aa[i]);
                acc[i][0] = fma2(ap, bp0, acc[i][0]);
                acc[i][1] = fma2(ap, bp1, acc[i][1]);
                acc[i][2] = fma2(ap, bp2, acc[i][2]);
                acc[i][3] = fma2(ap, bp3, acc[i][3]);
            }
        }
    }
#pragma unroll
    for (int i = 0; i < 8; i++) {
        int row = m0 + ty * 8 + i;
        float brow = __ldg(b_ih + row);
        float out[8]; float2 v;
        v = up2(acc[i][0]); out[0] = v.x; out[1] = v.y;
        v = up2(acc[i][1]); out[2] = v.x; out[3] = v.y;
        v = up2(acc[i][2]); out[4] = v.x; out[5] = v.y;
        v = up2(acc[i][3]); out[6] = v.x; out[7] = v.y;
#pragma unroll
        for (int j = 0; j < 8; j++) out[j] += brow;
        float4* dst = (float4*)(C + (size_t)row * BSZ + tx * 8);
        dst[0] = make_float4(out[0], out[1], out[2], out[3]);
        dst[1] = make_float4(out[4], out[5], out[6], out[7]);
    }
}

// ---------------- K4a: he = relu(hs @ W_he^T + b_he) (v11 form) ----------------
__global__ void __launch_bounds__(256) k4a_he(const float* __restrict__ W_he,
                                              const float* __restrict__ b_he) {
    __shared__ float As[16][128];
    __shared__ float Bs[16][128];
    const int tid = threadIdx.x;
    const int m0 = blockIdx.x * 128, n0 = 0;
    const float* A = g_hs;
    const float* B = W_he;
    const int lr = tid >> 1, ls = (tid & 1) * 8;
    const int tx = tid & 15, ty = tid >> 4;
    ull acc[8][4];
#pragma unroll
    for (int i = 0; i < 8; i++)
#pragma unroll
        for (int j = 0; j < 4; j++) acc[i][j] = 0ull;

    const float* Ap = A + (size_t)(m0 + lr) * HSZ + ls;
    const float* Bp = B + (size_t)(n0 + lr) * HSZ + ls;

    for (int kt = 0; kt < HSZ; kt += 16) {
        float4 a0 = *(const float4*)(Ap + kt);
        float4 a1 = *(const float4*)(Ap + kt + 4);
        float4 b0 = *(const float4*)(Bp + kt);
        float4 b1 = *(const float4*)(Bp + kt + 4);
        __syncthreads();
        As[ls + 0][lr] = a0.x; As[ls + 1][lr] = a0.y; As[ls + 2][lr] = a0.z; As[ls + 3][lr] = a0.w;
        As[ls + 4][lr] = a1.x; As[ls + 5][lr] = a1.y; As[ls + 6][lr] = a1.z; As[ls + 7][lr] = a1.w;
        Bs[ls + 0][lr] = b0.x; Bs[ls + 1][lr] = b0.y; Bs[ls + 2][lr] = b0.z; Bs[ls + 3][lr] = b0.w;
        Bs[ls + 4][lr] = b1.x; Bs[ls + 5][lr] = b1.y; Bs[ls + 6][lr] = b1.z; Bs[ls + 7][lr] = b1.w;
        __syncthreads();
#pragma unroll
        for (int k = 0; k < 16; k++) {
            float4 av0 = *(const float4*)&As[k][ty * 8];
            float4 av1 = *(const float4*)&As[k][ty * 8 + 4];
            float4 bv0 = *(const float4*)&Bs[k][tx * 8];
            float4 bv1 = *(const float4*)&Bs[k][tx * 8 + 4];
            ull bp0 = pk2(bv0.x, bv0.y), bp1 = pk2(bv0.z, bv0.w);
            ull bp2 = pk2(bv1.x, bv1.y), bp3 = pk2(bv1.z, bv1.w);
            float aa[8] = {av0.x, av0.y, av0.z, av0.w, av1.x, av1.y, av1.z, av1.w};
#pragma unroll
            for (int i = 0; i < 8; i++) {
                ull ap = pk2(aa[i], aa[i]);
                acc[i][0] = fma2(ap, bp0, acc[i][0]);
                acc[i][1] = fma2(ap, bp1, acc[i][1]);
                acc[i][2] = fma2(ap, bp2, acc[i][2]);
                acc[i][3] = fma2(ap, bp3, acc[i][3]);
            }
        }
    }
    float bvals[8];
#pragma unroll
    for (int j = 0; j < 8; j++) bvals[j] = __ldg(b_he + n0 + tx * 8 + j);
#pragma unroll
    for (int i = 0; i < 8; i++) {
        int row = m0 + ty * 8 + i;
        float out[8]; float2 v;
        v = up2(acc[i][0]); out[0] = v.x; out[1] = v.y;
        v = up2(acc[i][1]); out[2] = v.x; out[3] = v.y;
        v = up2(acc[i][2]); out[4] = v.x; out[5] = v.y;
        v = up2(acc[i][3]); out[6] = v.x; out[7] = v.y;
#pragma unroll
        for (int j = 0; j < 8; j++) out[j] = fmaxf(out[j] + bvals[j], 0.f);
        float4* dst = (float4*)(g_he + (size_t)row * SSZ + n0 + tx * 8);
        dst[0] = make_float4(out[0], out[1], out[2], out[3]);
        dst[1] = make_float4(out[4], out[5], out[6], out[7]);
    }
}

// ---------------- K3: persistent GRU v13 — two-level barrier ----------------
__global__ void __launch_bounds__(512, 2) k3_gru(const float* __restrict__ W_hh,
                                                 const float* __restrict__ b_hh) {
    extern __shared__ __align__(16) ull smemBuf[];
    ull* sW = smemBuf;
    ull* sP = smemBuf + SW_ULL;

    const int tid = threadIdx.x;
    const int bg = blockIdx.x;               // 0..3
    const int ug = blockIdx.y;               // 0..63
    const int ubase = ug * 8;
    const int ibase = bg * 32;
    unsigned* subc = g_sub + bg * 8 * 32;    // 8 counters for this bg, 128B apart
    unsigned* my_sub = subc + (ug & 7) * 32;

    for (int e = tid; e < 512 * 4 * 3; e += 512) {
        int g = e % 3;
        int up_ = (e / 3) & 3;
        int k = e / 12;
        int j0 = ubase + 2 * up_;
        float w0 = W_hh[(size_t)(g * HSZ + j0) * HSZ + k];
        float w1 = W_hh[(size_t)(g * HSZ + j0 + 1) * HSZ + k];
        sW[(size_t)(k * 4 + up_) * 4 + g] = pk2(w0, w1);
    }

    const int iq = tid & 7;
    const int up = (tid >> 3) & 3;
    const int kq = tid >> 5;

    const int iqB = tid & 7;
    const int rB  = (tid >> 3) & 3;
    const int upB = (tid >> 5) & 3;
    const int iB  = ibase + 4 * iqB + rB;
    const int jB  = ubase + 2 * upB;
    float bR0 = 0.f, bR1 = 0.f, bZ0 = 0.f, bZ1 = 0.f, bN0 = 0.f, bN1 = 0.f;
    if (tid < 128) {
        bR0 = __ldg(b_hh + jB);            bR1 = __ldg(b_hh + jB + 1);
        bZ0 = __ldg(b_hh + HSZ + jB);      bZ1 = __ldg(b_hh + HSZ + jB + 1);
        const float* xb0 = g_xg + iB;
        pf_l2(xb0 + (size_t)(0 * HSZ + jB) * BSZ);
        pf_l2(xb0 + (size_t)(1 * HSZ + jB) * BSZ);
        pf_l2(xb0 + (size_t)(2 * HSZ + jB) * BSZ);
        bN0 = __ldg(b_hh + 2 * HSZ + jB);  bN1 = __ldg(b_hh + 2 * HSZ + jB + 1);
    }
    __syncthreads();

    for (int t = 0; t < NSTEP; t++) {
        const float* hT  = g_hsT + (size_t)t * HS_SLICE;
        float*       hTn = g_hsT + (size_t)(t + 1) * HS_SLICE;
        float*       hSn = g_hs  + (size_t)(t + 1) * HS_SLICE;

        if (tid < 128 && t + 1 < NSTEP) {
            const float* xb = g_xg + (size_t)(t + 1) * G3 * BSZ + iB;
            pf_l2(xb + (size_t)(0 * HSZ + jB) * BSZ);
            pf_l2(xb + (size_t)(0 * HSZ + jB + 1) * BSZ);
            pf_l2(xb + (size_t)(1 * HSZ + jB) * BSZ);
            pf_l2(xb + (size_t)(1 * HSZ + jB + 1) * BSZ);
            pf_l2(xb + (size_t)(2 * HSZ + jB) * BSZ);
            pf_l2(xb + (size_t)(2 * HSZ + jB + 1) * BSZ);
        }

        ull acc[3][4];
#pragma unroll
        for (int g = 0; g < 3; g++)
#pragma unroll
            for (int r = 0; r < 4; r++) acc[g][r] = 0ull;

        const float4* hb = (const float4*)hT + (size_t)(kq * 32) * 32 + bg * 8 + iq;
        const ull*    wb = sW + (size_t)(kq * 32) * 16 + up * 4;

#pragma unroll 4
        for (int c = 0; c < 32; c++) {
            float4 h = __ldg(hb + (size_t)c * 32);
            ull p0 = pk2(h.x, h.x), p1 = pk2(h.y, h.y);
            ull p2 = pk2(h.z, h.z), p3 = pk2(h.w, h.w);
            const ull* wp = wb + (size_t)c * 16;
            ulonglong2 wab = *(const ulonglong2*)wp;
            ull wc = wp[2];
            acc[0][0] = fma2(p0, wab.x, acc[0][0]);
            acc[0][1] = fma2(p1, wab.x, acc[0][1]);
            acc[0][2] = fma2(p2, wab.x, acc[0][2]);
            acc[0][3] = fma2(p3, wab.x, acc[0][3]);
            acc[1][0] = fma2(p0, wab.y, acc[1][0]);
            acc[1][1] = fma2(p1, wab.y, acc[1][1]);
            acc[1][2] = fma2(p2, wab.y, acc[1][2]);
            acc[1][3] = fma2(p3, wab.y, acc[1][3]);
            acc[2][0] = fma2(p0, wc, acc[2][0]);
            acc[2][1] = fma2(p1, wc, acc[2][1]);
            acc[2][2] = fma2(p2, wc, acc[2][2]);
            acc[2][3] = fma2(p3, wc, acc[2][3]);
        }
#pragma unroll
        for (int g = 0; g < 3; g++)
#pragma unroll
            for (int r = 0; r < 4; r++)
                sP[(size_t)((kq * 3 + g) * 4 + r) * 32 + up * 8 + iq] = acc[g][r];
        __syncthreads();

        if (tid < 128) {
            const float* xb = g_xg + (size_t)t * G3 * BSZ + iB;
            float xr0 = __ldg(xb + (size_t)(0 * HSZ + jB) * BSZ);
            float xr1 = __ldg(xb + (size_t)(0 * HSZ + jB + 1) * BSZ);
            float xz0 = __ldg(xb + (size_t)(1 * HSZ + jB) * BSZ);
            float xz1 = __ldg(xb + (size_t)(1 * HSZ + jB + 1) * BSZ);
            float xn0 = __ldg(xb + (size_t)(2 * HSZ + jB) * BSZ);
            float xn1 = __ldg(xb + (size_t)(2 * HSZ + jB + 1) * BSZ);
            float hp0 = __ldg(hT + (size_t)jB * BSZ + iB);
            float hp1 = __ldg(hT + (size_t)(jB + 1) * BSZ + iB);

            ull sr = 0ull, sz = 0ull, sn = 0ull;
            const ull* pb = sP + (size_t)rB * 32 + upB * 8 + iqB;
#pragma unroll 4
            for (int q = 0; q < 16; q++) {
                const ull* pq = pb + (size_t)q * 384;
                sr = add2(sr, pq[0]);
                sz = add2(sz, pq[128]);
                sn = add2(sn, pq[256]);
            }
            float2 hr = up2(sr), hz = up2(sz), hn = up2(sn);

            float r0 = sigm(xr0 + hr.x + bR0);
            float z0 = sigm(xz0 + hz.x + bZ0);
            float n0 = tanhf(xn0 + r0 * (hn.x + bN0));
            float o0 = (1.f - z0) * n0 + z0 * hp0;

            float r1 = sigm(xr1 + hr.y + bR1);
            float z1 = sigm(xz1 + hz.y + bZ1);
            float n1 = tanhf(xn1 + r1 * (hn.y + bN1));
            float o1 = (1.f - z1) * n1 + z1 * hp1;

            hTn[(size_t)jB * BSZ + iB]       = o0;
            hTn[(size_t)(jB + 1) * BSZ + iB] = o1;
            hSn[(size_t)iB * HSZ + jB]       = o0;
            hSn[(size_t)iB * HSZ + jB + 1]   = o1;
            __threadfence();                 // fence only the storing threads
        }
        __syncthreads();
        // ---- two-level per-bg barrier: 8 sub-counters x 8 arrivals each ----
        if (tid == 0) {
            atomicAdd(my_sub, 1u);
            unsigned tgt = 8u * (unsigned)(t + 1);
            for (;;) {
                unsigned ok = 1u;
#pragma unroll
                for (int q = 0; q < 8; q++)
                    ok &= (*(volatile unsigned*)&subc[q * 32] >= tgt) ? 1u : 0u;
                if (ok) break;
                __nanosleep(32);
            }
            __threadfence();
        }
        __syncthreads();
    }
}

// ---------------- K4b: per-event loss ----------------
__global__ void __launch_bounds__(256) k4b_loss(const float* __restrict__ x,
                                                const float* __restrict__ tin,
                                                const float* __restrict__ maskp,
                                                const float* __restrict__ W_mu,
                                                const float* __restrict__ b_mu,
                                                const float* __restrict__ W_lv,
                                                const float* __restrict__ b_lv,
                                                const float* __restrict__ h_infl,
                                                const float* __restrict__ ti_p,
                                                const float* __restrict__ bi_p) {
    __shared__ float s_he[8][SSZ];
    __shared__ float s_red[8];
    const int tid = threadIdx.x;
    const int w = tid >> 5, lane = tid & 31;
    const int q = blockIdx.x * 8 + w;
    const int t = (q >> 7) + 1;
    const int i = q & 127;
    const size_t row = (size_t)t * BSZ + i;

    ((float4*)s_he[w])[lane] = ((const float4*)(g_he + row * SSZ))[lane];
    __syncwarp();

    float p = 0.f;
#pragma unroll
    for (int kk = 0; kk < 4; kk++) {
        int k = lane + 32 * kk;
        p += s_he[w][k] * __ldg(h_infl + k);
    }
#pragma unroll
    for (int off = 16; off; off >>= 1) p += __shfl_xor_sync(0xffffffffu, p, off);

    float marker = 0.f;
    if (lane < MDIM) {
        float accm = __ldg(b_mu + lane);
        float accl = __ldg(b_lv + lane);
        const float4* wm = (const float4*)(W_mu + lane * SSZ);
        const float4* wl = (const float4*)(W_lv + lane * SSZ);
#pragma unroll 8
        for (int kk = 0; kk < 32; kk++) {
            float4 hev = ((const float4*)s_he[w])[kk];
            float4 a = __ldg(wm + kk);
            float4 b = __ldg(wl + kk);
            accm += hev.x * a.x + hev.y * a.y + hev.z * a.z + hev.w * a.w;
            accl += hev.x * b.x + hev.y * b.y + hev.z * b.z + hev.w * b.w;
        }
        float xv = __ldg(x + row * MDIM + lane);
        float sig = fmaxf(expf(0.5f * accl), 0.01f);
        float d = (xv - accm) / sig;
        marker = -0.5f * d * d - logf(sig) - 0.5f * LOG2PI;
    }
#pragma unroll
    for (int off = 16; off; off >>= 1) marker += __shfl_xor_sync(0xffffffffu, marker, off);

    if (lane == 0) {
        float ti = __ldg(ti_p);
        float bi = __ldg(bi_p);
        float dt = __ldg(tin + row * 2 + 1);
        float term1 = p + ti * dt + bi;
        float time_ll = term1 + (expf(p + bi) - expf(term1)) / ti;
        float m = __ldg(maskp + row);
        s_red[w] = (-time_ll - marker) * m;
    }
    __syncthreads();
    if (tid == 0) {
        float s = 0.f;
#pragma unroll
        for (int k = 0; k < 8; k++) s += s_red[k];
        g_partial[blockIdx.x] = s;
    }
}

// ---------------- K5: deterministic final reduce ----------------
__global__ void __launch_bounds__(256) k5_reduce(float* __restrict__ out) {
    __shared__ float s[256];
    const int tid = threadIdx.x;
    float a = 0.f;
    for (int idx = tid; idx < NB4B; idx += 256) a += g_partial[idx];
    s[tid] = a;
    __syncthreads();
    for (int off = 128; off; off >>= 1) {
        if (tid < off) s[tid] += s[tid + off];
        __syncthreads();
    }
    if (tid == 0) out[0] = s[0];
}

// ---------------- launch ----------------
extern "C" void kernel_launch(void* const* d_in, const int* in_sizes, int n_in,
                              void* d_out, int out_size) {
    const float* x       = (const float*)d_in[0];
    const float* tin     = (const float*)d_in[1];
    const float* maskp   = (const float*)d_in[2];
    const float* W_embed = (const float*)d_in[3];
    const float* b_embed = (const float*)d_in[4];
    const float* W_ih    = (const float*)d_in[5];
    const float* b_ih    = (const float*)d_in[6];
    const float* W_hh    = (const float*)d_in[7];
    const float* b_hh    = (const float*)d_in[8];
    const float* W_he    = (const float*)d_in[9];
    const float* b_he    = (const float*)d_in[10];
    const float* W_mu    = (const float*)d_in[11];
    const float* b_mu    = (const float*)d_in[12];
    const float* W_lv    = (const float*)d_in[13];
    const float* b_lv    = (const float*)d_in[14];
    const float* h_infl  = (const float*)d_in[15];
    const float* ti_p    = (const float*)d_in[16];
    const float* bi_p    = (const float*)d_in[17];
    float* out = (float*)d_out;

    static bool attr_set = false;
    if (!attr_set) {
        cudaFuncSetAttribute(k3_gru, cudaFuncAttributeMaxDynamicSharedMemorySize, K3_SMEM_BYTES);
        attr_set = true;
    }

    k0_init<<<256, 256>>>();
    k1_embed<<<1024, 256>>>(x, W_embed, b_embed);
    k2_gatesT<<<dim3(12, 1, 512), 256>>>(W_ih, b_ih);
    k3_gru<<<dim3(4, 64), 512, K3_SMEM_BYTES>>>(W_hh, b_hh);
    k4a_he<<<dim3(512, 1), 256>>>(W_he, b_he);
    k4b_loss<<<NB4B, 256>>>(x, tin, maskp, W_mu, b_mu, W_lv, b_lv, h_infl, ti_p, bi_p);
    k5_reduce<<<1, 256>>>(out);
}

// round 15
// speedup vs baseline: 1.3586x; 1.3586x over previous
#include <cuda_runtime.h>

typedef unsigned long long ull;

#define TLEN 512
#define BSZ  128
#define MDIM 31
#define HSZ  512
#define ESZ  256
#define SSZ  128
#define G3   1536
#define TB   65536
#define NSTEP 511
#define HS_SLICE 65536
#define NB4B  8176
#define LOG2PI 1.8378770664093453f

#define SW_ULL    8192          // [512 k][4 up][4 slots(3 used)] = 64KB
#define SPART_ULL 6144          // [16 kq][3 g][4 r][4 up][8 iq]  = 48KB
#define K3_SMEM_BYTES ((SW_ULL + SPART_ULL) * 8)   // 114688 (x2/SM = 229376)

// ---------------- scratch ----------------
__device__ float g_phi[TB * ESZ];                    // [t*128+i][e]
__device__ float g_xg[(size_t)TB * G3];              // [t][col(1536)][i(128)]
__device__ float g_hs[(size_t)TLEN * BSZ * HSZ];     // [t][i][k]
__device__ float g_hsT[(size_t)TLEN * BSZ * HSZ];    // [t][k][i]
__device__ float g_he[(size_t)TB * SSZ];
__device__ float g_partial[NB4B];
__device__ unsigned g_arrive4[4 * 32];               // one counter per bg, 128B apart

// ---------------- helpers ----------------
__device__ __forceinline__ ull pk2(float x, float y) {
    ull r; asm("mov.b64 %0, {%1, %2};" : "=l"(r) : "f"(x), "f"(y)); return r;
}
__device__ __forceinline__ ull fma2(ull a, ull b, ull c) {
    ull d; asm("fma.rn.f32x2 %0, %1, %2, %3;" : "=l"(d) : "l"(a), "l"(b), "l"(c)); return d;
}
__device__ __forceinline__ ull add2(ull a, ull b) {
    ull d; asm("add.rn.f32x2 %0, %1, %2;" : "=l"(d) : "l"(a), "l"(b)); return d;
}
__device__ __forceinline__ float2 up2(ull v) {
    float2 f; asm("mov.b64 {%0, %1}, %2;" : "=f"(f.x), "=f"(f.y) : "l"(v)); return f;
}
__device__ __forceinline__ float sigm(float v) { return 1.f / (1.f + __expf(-v)); }
__device__ __forceinline__ void pf_l2(const void* p) {
    asm volatile("prefetch.global.L2 [%0];" :: "l"(p));
}

// ---------------- K0: init ----------------
__global__ void k0_init() {
    int idx = blockIdx.x * 256 + threadIdx.x;
    if (idx < HS_SLICE) { g_hsT[idx] = 0.f; g_hs[idx] = 0.f; }
    if (idx < 4 * 32) g_arrive4[idx] = 0u;
}

// ---------------- K1: phi = relu(x @ W_embed^T + b) ----------------
__global__ void __launch_bounds__(256) k1_embed(const float* __restrict__ x,
                                                const float* __restrict__ W_embed,
                                                const float* __restrict__ b_embed) {
    __shared__ float sx[64][32];
    const int tid = threadIdx.x;
    const int row0 = blockIdx.x * 64;
    for (int idx = tid; idx < 64 * MDIM; idx += 256) {
        int r = idx / MDIM, c = idx - r * MDIM;
        sx[r][c] = x[(size_t)(row0 + r) * MDIM + c];
    }
    float wreg[MDIM];
    const float* wp = W_embed + tid * MDIM;
#pragma unroll
    for (int k = 0; k < MDIM; k++) wreg[k] = __ldg(wp + k);
    float bb = __ldg(b_embed + tid);
    __syncthreads();
#pragma unroll 4
    for (int r = 0; r < 64; r++) {
        float acc = bb;
#pragma unroll
        for (int k = 0; k < MDIM; k++) acc += sx[r][k] * wreg[k];
        g_phi[(size_t)(row0 + r) * ESZ + tid] = fmaxf(acc, 0.f);
    }
}

// ---------------- K2: xgT[t][col][i] ----------------
__global__ void __launch_bounds__(256) k2_gatesT(const float* __restrict__ W_ih,
                                                 const float* __restrict__ b_ih) {
    __shared__ float As[16][128];
    __shared__ float Bs[16][128];
    const int tid = threadIdx.x;
    const int t = blockIdx.z;
    const int m0 = blockIdx.x * 128;
    const float* A = W_ih;
    const float* B = g_phi + (size_t)t * BSZ * ESZ;
    float*       C = g_xg  + (size_t)t * G3 * BSZ;
    const int lr = tid >> 1, ls = (tid & 1) * 8;
    const int tx = tid & 15, ty = tid >> 4;
    ull acc[8][4];
#pragma unroll
    for (int i = 0; i < 8; i++)
#pragma unroll
        for (int j = 0; j < 4; j++) acc[i][j] = 0ull;

    const float* Ap = A + (size_t)(m0 + lr) * ESZ + ls;
    const float* Bp = B + (size_t)lr * ESZ + ls;

    for (int kt = 0; kt < ESZ; kt += 16) {
        float4 a0 = *(const float4*)(Ap + kt);
        float4 a1 = *(const float4*)(Ap + kt + 4);
        float4 b0 = *(const float4*)(Bp + kt);
        float4 b1 = *(const float4*)(Bp + kt + 4);
        __syncthreads();
        As[ls + 0][lr] = a0.x; As[ls + 1][lr] = a0.y; As[ls + 2][lr] = a0.z; As[ls + 3][lr] = a0.w;
        As[ls + 4][lr] = a1.x; As[ls + 5][lr] = a1.y; As[ls + 6][lr] = a1.z; As[ls + 7][lr] = a1.w;
        Bs[ls + 0][lr] = b0.x; Bs[ls + 1][lr] = b0.y; Bs[ls + 2][lr] = b0.z; Bs[ls + 3][lr] = b0.w;
        Bs[ls + 4][lr] = b1.x; Bs[ls + 5][lr] = b1.y; Bs[ls + 6][lr] = b1.z; Bs[ls + 7][lr] = b1.w;
        __syncthreads();
#pragma unroll
        for (int k = 0; k < 16; k++) {
            float4 av0 = *(const float4*)&As[k][ty * 8];
            float4 av1 = *(const float4*)&As[k][ty * 8 + 4];
            float4 bv0 = *(const float4*)&Bs[k][tx * 8];
            float4 bv1 = *(const float4*)&Bs[k][tx * 8 + 4];
            ull bp0 = pk2(bv0.x, bv0.y), bp1 = pk2(bv0.z, bv0.w);
            ull bp2 = pk2(bv1.x, bv1.y), bp3 = pk2(bv1.z, bv1.w);
            float aa[8] = {av0.x, av0.y, av0.z, av0.w, av1.x, av1.y, av1.z, av1.w};
#pragma unroll
            for (int i = 0; i < 8; i++) {
                ull ap = pk2(aa[i], aa[i]);
                acc[i][0] = fma2(ap, bp0, acc[i][0]);
                acc[i][1] = fma2(ap, bp1, acc[i][1]);
                acc[i][2] = fma2(ap, bp2, acc[i][2]);
                acc[i][3] = fma2(ap, bp3, acc[i][3]);
            }
        }
    }
#pragma unroll
    for (int i = 0; i < 8; i++) {
        int row = m0 + ty * 8 + i;
        float brow = __ldg(b_ih + row);
        float out[8]; float2 v;
        v = up2(acc[i][0]); out[0] = v.x; out[1] = v.y;
        v = up2(acc[i][1]); out[2] = v.x; out[3] = v.y;
        v = up2(acc[i][2]); out[4] = v.x; out[5] = v.y;
        v = up2(acc[i][3]); out[6] = v.x; out[7] = v.y;
#pragma unroll
        for (int j = 0; j < 8; j++) out[j] += brow;
        float4* dst = (float4*)(C + (size_t)row * BSZ + tx * 8);
        dst[0] = make_float4(out[0], out[1], out[2], out[3]);
        dst[1] = make_float4(out[4], out[5], out[6], out[7]);
    }
}

// ---------------- K4a: he = relu(hs @ W_he^T + b_he) ----------------
__global__ void __launch_bounds__(256) k4a_he(const float* __restrict__ W_he,
                                              const float* __restrict__ b_he) {
    __shared__ float As[16][128];
    __shared__ float Bs[16][128];
    const int tid = threadIdx.x;
    const int m0 = blockIdx.x * 128, n0 = 0;
    const float* A = g_hs;
    const float* B = W_he;
    const int lr = tid >> 1, ls = (tid & 1) * 8;
    const int tx = tid & 15, ty = tid >> 4;
    ull acc[8][4];
#pragma unroll
    for (int i = 0; i < 8; i++)
#pragma unroll
        for (int j = 0; j < 4; j++) acc[i][j] = 0ull;

    const float* Ap = A + (size_t)(m0 + lr) * HSZ + ls;
    const float* Bp = B + (size_t)(n0 + lr) * HSZ + ls;

    for (int kt = 0; kt < HSZ; kt += 16) {
        float4 a0 = *(const float4*)(Ap + kt);
        float4 a1 = *(const float4*)(Ap + kt + 4);
        float4 b0 = *(const float4*)(Bp + kt);
        float4 b1 = *(const float4*)(Bp + kt + 4);
        __syncthreads();
        As[ls + 0][lr] = a0.x; As[ls + 1][lr] = a0.y; As[ls + 2][lr] = a0.z; As[ls + 3][lr] = a0.w;
        As[ls + 4][lr] = a1.x; As[ls + 5][lr] = a1.y; As[ls + 6][lr] = a1.z; As[ls + 7][lr] = a1.w;
        Bs[ls + 0][lr] = b0.x; Bs[ls + 1][lr] = b0.y; Bs[ls + 2][lr] = b0.z; Bs[ls + 3][lr] = b0.w;
        Bs[ls + 4][lr] = b1.x; Bs[ls + 5][lr] = b1.y; Bs[ls + 6][lr] = b1.z; Bs[ls + 7][lr] = b1.w;
        __syncthreads();
#pragma unroll
        for (int k = 0; k < 16; k++) {
            float4 av0 = *(const float4*)&As[k][ty * 8];
            float4 av1 = *(const float4*)&As[k][ty * 8 + 4];
            float4 bv0 = *(const float4*)&Bs[k][tx * 8];
            float4 bv1 = *(const float4*)&Bs[k][tx * 8 + 4];
            ull bp0 = pk2(bv0.x, bv0.y), bp1 = pk2(bv0.z, bv0.w);
            ull bp2 = pk2(bv1.x, bv1.y), bp3 = pk2(bv1.z, bv1.w);
            float aa[8] = {av0.x, av0.y, av0.z, av0.w, av1.x, av1.y, av1.z, av1.w};
#pragma unroll
            for (int i = 0; i < 8; i++) {
                ull ap = pk2(aa[i], aa[i]);
                acc[i][0] = fma2(ap, bp0, acc[i][0]);
                acc[i][1] = fma2(ap, bp1, acc[i][1]);
                acc[i][2] = fma2(ap, bp2, acc[i][2]);
                acc[i][3] = fma2(ap, bp3, acc[i][3]);
            }
        }
    }
    float bvals[8];
#pragma unroll
    for (int j = 0; j < 8; j++) bvals[j] = __ldg(b_he + n0 + tx * 8 + j);
#pragma unroll
    for (int i = 0; i < 8; i++) {
        int row = m0 + ty * 8 + i;
        float out[8]; float2 v;
        v = up2(acc[i][0]); out[0] = v.x; out[1] = v.y;
        v = up2(acc[i][1]); out[2] = v.x; out[3] = v.y;
        v = up2(acc[i][2]); out[4] = v.x; out[5] = v.y;
        v = up2(acc[i][3]); out[6] = v.x; out[7] = v.y;
#pragma unroll
        for (int j = 0; j < 8; j++) out[j] = fmaxf(out[j] + bvals[j], 0.f);
        float4* dst = (float4*)(g_he + (size_t)row * SSZ + n0 + tx * 8);
        dst[0] = make_float4(out[0], out[1], out[2], out[3]);
        dst[1] = make_float4(out[4], out[5], out[6], out[7]);
    }
}

// ---------------- K3: persistent GRU v14 — v11 + conflict-free reduce identity ----------------
// Grid (4 bg, 64 ug) = 256 blocks, 512 threads, 112KB smem -> 2 blocks/SM.
// Epilogue identity: upB uses bits [3:4], rB uses bits [5:6] so a warp's 32 lanes
// read contiguous ull addresses (up*8+iq = 0..31) -> conflict-free LDS.64.
__global__ void __launch_bounds__(512, 2) k3_gru(const float* __restrict__ W_hh,
                                                 const float* __restrict__ b_hh) {
    extern __shared__ __align__(16) ull smemBuf[];
    ull* sW = smemBuf;
    ull* sP = smemBuf + SW_ULL;

    const int tid = threadIdx.x;
    const int bg = blockIdx.x;
    const int ug = blockIdx.y;
    const int ubase = ug * 8;
    const int ibase = bg * 32;
    unsigned* my_ctr = &g_arrive4[bg * 32];

    for (int e = tid; e < 512 * 4 * 3; e += 512) {
        int g = e % 3;
        int up_ = (e / 3) & 3;
        int k = e / 12;
        int j0 = ubase + 2 * up_;
        float w0 = W_hh[(size_t)(g * HSZ + j0) * HSZ + k];
        float w1 = W_hh[(size_t)(g * HSZ + j0 + 1) * HSZ + k];
        sW[(size_t)(k * 4 + up_) * 4 + g] = pk2(w0, w1);
    }

    const int iq = tid & 7;
    const int up = (tid >> 3) & 3;
    const int kq = tid >> 5;

    // epilogue identity (tid < 128): SWAPPED bit fields vs v11 (conflict-free LDS)
    const int iqB = tid & 7;
    const int upB = (tid >> 3) & 3;          // was rB's bits in v11
    const int rB  = (tid >> 5) & 3;          // was upB's bits in v11
    const int iB  = ibase + 4 * iqB + rB;
    const int jB  = ubase + 2 * upB;
    float bR0 = 0.f, bR1 = 0.f, bZ0 = 0.f, bZ1 = 0.f, bN0 = 0.f, bN1 = 0.f;
    if (tid < 128) {
        bR0 = __ldg(b_hh + jB);            bR1 = __ldg(b_hh + jB + 1);
        bZ0 = __ldg(b_hh + HSZ + jB);      bZ1 = __ldg(b_hh + HSZ + jB + 1);
        const float* xb0 = g_xg + iB;
        pf_l2(xb0 + (size_t)(0 * HSZ + jB) * BSZ);
        pf_l2(xb0 + (size_t)(1 * HSZ + jB) * BSZ);
        pf_l2(xb0 + (size_t)(2 * HSZ + jB) * BSZ);
        bN0 = __ldg(b_hh + 2 * HSZ + jB);  bN1 = __ldg(b_hh + 2 * HSZ + jB + 1);
    }
    __syncthreads();

    for (int t = 0; t < NSTEP; t++) {
        const float* hT  = g_hsT + (size_t)t * HS_SLICE;
        float*       hTn = g_hsT + (size_t)(t + 1) * HS_SLICE;
        float*       hSn = g_hs  + (size_t)(t + 1) * HS_SLICE;

        if (tid < 128 && t + 1 < NSTEP) {
            const float* xb = g_xg + (size_t)(t + 1) * G3 * BSZ + iB;
            pf_l2(xb + (size_t)(0 * HSZ + jB) * BSZ);
            pf_l2(xb + (size_t)(0 * HSZ + jB + 1) * BSZ);
            pf_l2(xb + (size_t)(1 * HSZ + jB) * BSZ);
            pf_l2(xb + (size_t)(1 * HSZ + jB + 1) * BSZ);
            pf_l2(xb + (size_t)(2 * HSZ + jB) * BSZ);
            pf_l2(xb + (size_t)(2 * HSZ + jB + 1) * BSZ);
        }

        ull acc[3][4];
#pragma unroll
        for (int g = 0; g < 3; g++)
#pragma unroll
            for (int r = 0; r < 4; r++) acc[g][r] = 0ull;

        const float4* hb = (const float4*)hT + (size_t)(kq * 32) * 32 + bg * 8 + iq;
        const ull*    wb = sW + (size_t)(kq * 32) * 16 + up * 4;

#pragma unroll 4
        for (int c = 0; c < 32; c++) {
            float4 h = __ldg(hb + (size_t)c * 32);
            ull p0 = pk2(h.x, h.x), p1 = pk2(h.y, h.y);
            ull p2 = pk2(h.z, h.z), p3 = pk2(h.w, h.w);
            const ull* wp = wb + (size_t)c * 16;
            ulonglong2 wab = *(const ulonglong2*)wp;
            ull wc = wp[2];
            acc[0][0] = fma2(p0, wab.x, acc[0][0]);
            acc[0][1] = fma2(p1, wab.x, acc[0][1]);
            acc[0][2] = fma2(p2, wab.x, acc[0][2]);
            acc[0][3] = fma2(p3, wab.x, acc[0][3]);
            acc[1][0] = fma2(p0, wab.y, acc[1][0]);
            acc[1][1] = fma2(p1, wab.y, acc[1][1]);
            acc[1][2] = fma2(p2, wab.y, acc[1][2]);
            acc[1][3] = fma2(p3, wab.y, acc[1][3]);
            acc[2][0] = fma2(p0, wc, acc[2][0]);
            acc[2][1] = fma2(p1, wc, acc[2][1]);
            acc[2][2] = fma2(p2, wc, acc[2][2]);
            acc[2][3] = fma2(p3, wc, acc[2][3]);
        }
#pragma unroll
        for (int g = 0; g < 3; g++)
#pragma unroll
            for (int r = 0; r < 4; r++)
                sP[(size_t)((kq * 3 + g) * 4 + r) * 32 + up * 8 + iq] = acc[g][r];
        __syncthreads();

        if (tid < 128) {
            const float* xb = g_xg + (size_t)t * G3 * BSZ + iB;
            float xr0 = __ldg(xb + (size_t)(0 * HSZ + jB) * BSZ);
            float xr1 = __ldg(xb + (size_t)(0 * HSZ + jB + 1) * BSZ);
            float xz0 = __ldg(xb + (size_t)(1 * HSZ + jB) * BSZ);
            float xz1 = __ldg(xb + (size_t)(1 * HSZ + jB + 1) * BSZ);
            float xn0 = __ldg(xb + (size_t)(2 * HSZ + jB) * BSZ);
            float xn1 = __ldg(xb + (size_t)(2 * HSZ + jB + 1) * BSZ);
            float hp0 = __ldg(hT + (size_t)jB * BSZ + iB);
            float hp1 = __ldg(hT + (size_t)(jB + 1) * BSZ + iB);

            ull sr = 0ull, sz = 0ull, sn = 0ull;
            const ull* pb = sP + (size_t)rB * 32 + upB * 8 + iqB;
#pragma unroll 4
            for (int q = 0; q < 16; q++) {
                const ull* pq = pb + (size_t)q * 384;       // kq stride = 3*4*32
                sr = add2(sr, pq[0]);
                sz = add2(sz, pq[128]);                     // g stride = 4*32
                sn = add2(sn, pq[256]);
            }
            float2 hr = up2(sr), hz = up2(sz), hn = up2(sn);

            float r0 = sigm(xr0 + hr.x + bR0);
            float z0 = sigm(xz0 + hz.x + bZ0);
            float n0 = tanhf(xn0 + r0 * (hn.x + bN0));
            float o0 = (1.f - z0) * n0 + z0 * hp0;

            float r1 = sigm(xr1 + hr.y + bR1);
            float z1 = sigm(xz1 + hz.y + bZ1);
            float n1 = tanhf(xn1 + r1 * (hn.y + bN1));
            float o1 = (1.f - z1) * n1 + z1 * hp1;

            hTn[(size_t)jB * BSZ + iB]       = o0;
            hTn[(size_t)(jB + 1) * BSZ + iB] = o1;
            hSn[(size_t)iB * HSZ + jB]       = o0;
            hSn[(size_t)iB * HSZ + jB + 1]   = o1;
        }
        __threadfence();
        __syncthreads();
        if (tid == 0) {
            atomicAdd(my_ctr, 1u);
            unsigned target = 64u * (unsigned)(t + 1);
            while (*(volatile unsigned*)my_ctr < target) { __nanosleep(32); }
            __threadfence();
        }
        __syncthreads();
    }
}

// ---------------- K4b: per-event loss ----------------
__global__ void __launch_bounds__(256) k4b_loss(const float* __restrict__ x,
                                                const float* __restrict__ tin,
                                                const float* __restrict__ maskp,
                                                const float* __restrict__ W_mu,
                                                const float* __restrict__ b_mu,
                                                const float* __restrict__ W_lv,
                                                const float* __restrict__ b_lv,
                                                const float* __restrict__ h_infl,
                                                const float* __restrict__ ti_p,
                                                const float* __restrict__ bi_p) {
    __shared__ float s_he[8][SSZ];
    __shared__ float s_red[8];
    const int tid = threadIdx.x;
    const int w = tid >> 5, lane = tid & 31;
    const int q = blockIdx.x * 8 + w;
    const int t = (q >> 7) + 1;
    const int i = q & 127;
    const size_t row = (size_t)t * BSZ + i;

    ((float4*)s_he[w])[lane] = ((const float4*)(g_he + row * SSZ))[lane];
    __syncwarp();

    float p = 0.f;
#pragma unroll
    for (int kk = 0; kk < 4; kk++) {
        int k = lane + 32 * kk;
        p += s_he[w][k] * __ldg(h_infl + k);
    }
#pragma unroll
    for (int off = 16; off; off >>= 1) p += __shfl_xor_sync(0xffffffffu, p, off);

    float marker = 0.f;
    if (lane < MDIM) {
        float accm = __ldg(b_mu + lane);
        float accl = __ldg(b_lv + lane);
        const float4* wm = (const float4*)(W_mu + lane * SSZ);
        const float4* wl = (const float4*)(W_lv + lane * SSZ);
#pragma unroll 8
        for (int kk = 0; kk < 32; kk++) {
            float4 hev = ((const float4*)s_he[w])[kk];
            float4 a = __ldg(wm + kk);
            float4 b = __ldg(wl + kk);
            accm += hev.x * a.x + hev.y * a.y + hev.z * a.z + hev.w * a.w;
            accl += hev.x * b.x + hev.y * b.y + hev.z * b.z + hev.w * b.w;
        }
        float xv = __ldg(x + row * MDIM + lane);
        float sig = fmaxf(expf(0.5f * accl), 0.01f);
        float d = (xv - accm) / sig;
        marker = -0.5f * d * d - logf(sig) - 0.5f * LOG2PI;
    }
#pragma unroll
    for (int off = 16; off; off >>= 1) marker += __shfl_xor_sync(0xffffffffu, marker, off);

    if (lane == 0) {
        float ti = __ldg(ti_p);
        float bi = __ldg(bi_p);
        float dt = __ldg(tin + row * 2 + 1);
        float term1 = p + ti * dt + bi;
        float time_ll = term1 + (expf(p + bi) - expf(term1)) / ti;
        float m = __ldg(maskp + row);
        s_red[w] = (-time_ll - marker) * m;
    }
    __syncthreads();
    if (tid == 0) {
        float s = 0.f;
#pragma unroll
        for (int k = 0; k < 8; k++) s += s_red[k];
        g_partial[blockIdx.x] = s;
    }
}

// ---------------- K5: deterministic final reduce ----------------
__global__ void __launch_bounds__(256) k5_reduce(float* __restrict__ out) {
    __shared__ float s[256];
    const int tid = threadIdx.x;
    float a = 0.f;
    for (int idx = tid; idx < NB4B; idx += 256) a += g_partial[idx];
    s[tid] = a;
    __syncthreads();
    for (int off = 128; off; off >>= 1) {
        if (tid < off) s[tid] += s[tid + off];
        __syncthreads();
    }
    if (tid == 0) out[0] = s[0];
}

// ---------------- launch ----------------
extern "C" void kernel_launch(void* const* d_in, const int* in_sizes, int n_in,
                              void* d_out, int out_size) {
    const float* x       = (const float*)d_in[0];
    const float* tin     = (const float*)d_in[1];
    const float* maskp   = (const float*)d_in[2];
    const float* W_embed = (const float*)d_in[3];
    const float* b_embed = (const float*)d_in[4];
    const float* W_ih    = (const float*)d_in[5];
    const float* b_ih    = (const float*)d_in[6];
    const float* W_hh    = (const float*)d_in[7];
    const float* b_hh    = (const float*)d_in[8];
    const float* W_he    = (const float*)d_in[9];
    const float* b_he    = (const float*)d_in[10];
    const float* W_mu    = (const float*)d_in[11];
    const float* b_mu    = (const float*)d_in[12];
    const float* W_lv    = (const float*)d_in[13];
    const float* b_lv    = (const float*)d_in[14];
    const float* h_infl  = (const float*)d_in[15];
    const float* ti_p    = (const float*)d_in[16];
    const float* bi_p    = (const float*)d_in[17];
    float* out = (float*)d_out;

    static bool attr_set = false;
    if (!attr_set) {
        cudaFuncSetAttribute(k3_gru, cudaFuncAttributeMaxDynamicSharedMemorySize, K3_SMEM_BYTES);
        attr_set = true;
    }

    k0_init<<<256, 256>>>();
    k1_embed<<<1024, 256>>>(x, W_embed, b_embed);
    k2_gatesT<<<dim3(12, 1, 512), 256>>>(W_ih, b_ih);
    k3_gru<<<dim3(4, 64), 512, K3_SMEM_BYTES>>>(W_hh, b_hh);
    k4a_he<<<dim3(512, 1), 256>>>(W_he, b_he);
    k4b_loss<<<NB4B, 256>>>(x, tin, maskp, W_mu, b_mu, W_lv, b_lv, h_infl, ti_p, bi_p);
    k5_reduce<<<1, 256>>>(out);
}

// round 16
// speedup vs baseline: 1.3805x; 1.0162x over previous
#include <cuda_runtime.h>

typedef unsigned long long ull;

#define TLEN 512
#define BSZ  128
#define MDIM 31
#define HSZ  512
#define ESZ  256
#define SSZ  128
#define G3   1536
#define TB   65536
#define NSTEP 511
#define HS_SLICE 65536
#define NB4B  8176
#define LOG2PI 1.8378770664093453f

#define SW_ULL    8192          // [512 k][4 up][4 slots(3 used)] = 64KB
#define SPART_ULL 6144          // [16 kq][3 g][4 r][4 up][8 iq]  = 48KB
#define K3_SMEM_BYTES ((SW_ULL + SPART_ULL) * 8)   // 114688 (x2/SM = 229376)

// ---------------- scratch ----------------
__device__ float g_phi[TB * ESZ];                    // [t*128+i][e]
__device__ float g_xg[(size_t)TB * G3];              // [t][col(1536)][i(128)]
__device__ float g_hsT[(size_t)TLEN * BSZ * HSZ];    // [t][k][i]
__device__ float g_he[(size_t)TB * SSZ];
__device__ float g_partial[NB4B];
__device__ unsigned g_arrive4[4 * 32];               // one counter per bg, 128B apart

// ---------------- helpers ----------------
__device__ __forceinline__ ull pk2(float x, float y) {
    ull r; asm("mov.b64 %0, {%1, %2};" : "=l"(r) : "f"(x), "f"(y)); return r;
}
__device__ __forceinline__ ull fma2(ull a, ull b, ull c) {
    ull d; asm("fma.rn.f32x2 %0, %1, %2, %3;" : "=l"(d) : "l"(a), "l"(b), "l"(c)); return d;
}
__device__ __forceinline__ ull add2(ull a, ull b) {
    ull d; asm("add.rn.f32x2 %0, %1, %2;" : "=l"(d) : "l"(a), "l"(b)); return d;
}
__device__ __forceinline__ float2 up2(ull v) {
    float2 f; asm("mov.b64 {%0, %1}, %2;" : "=f"(f.x), "=f"(f.y) : "l"(v)); return f;
}
__device__ __forceinline__ float sigm(float v) { return 1.f / (1.f + __expf(-v)); }
__device__ __forceinline__ void pf_l2(const void* p) {
    asm volatile("prefetch.global.L2 [%0];" :: "l"(p));
}

// ---------------- K0: init ----------------
__global__ void k0_init() {
    int idx = blockIdx.x * 256 + threadIdx.x;
    if (idx < HS_SLICE) g_hsT[idx] = 0.f;
    if (idx < 4 * 32) g_arrive4[idx] = 0u;
}

// ---------------- K1: phi = relu(x @ W_embed^T + b) ----------------
__global__ void __launch_bounds__(256) k1_embed(const float* __restrict__ x,
                                                const float* __restrict__ W_embed,
                                                const float* __restrict__ b_embed) {
    __shared__ float sx[64][32];
    const int tid = threadIdx.x;
    const int row0 = blockIdx.x * 64;
    for (int idx = tid; idx < 64 * MDIM; idx += 256) {
        int r = idx / MDIM, c = idx - r * MDIM;
        sx[r][c] = x[(size_t)(row0 + r) * MDIM + c];
    }
    float wreg[MDIM];
    const float* wp = W_embed + tid * MDIM;
#pragma unroll
    for (int k = 0; k < MDIM; k++) wreg[k] = __ldg(wp + k);
    float bb = __ldg(b_embed + tid);
    __syncthreads();
#pragma unroll 4
    for (int r = 0; r < 64; r++) {
        float acc = bb;
#pragma unroll
        for (int k = 0; k < MDIM; k++) acc += sx[r][k] * wreg[k];
        g_phi[(size_t)(row0 + r) * ESZ + tid] = fmaxf(acc, 0.f);
    }
}

// ---------------- K2 v15: two t's per block, 8x16 microtile, reg-prefetch ----------------
// grid (12, 256): bx = col block (m0), by = t-pair. B rows = 256 (two t slices of phi).
// n mapping interleaved: n = tx*4 + jj*64 -> all b-LDS.128 lane-consecutive, conflict-free.
__global__ void __launch_bounds__(256) k2_gatesT(const float* __restrict__ W_ih,
                                                 const float* __restrict__ b_ih) {
    __shared__ float As[16][128];   // [k][col]
    __shared__ float Bs[16][256];   // [k][n]  n = (t-half, i)
    const int tid = threadIdx.x;
    const int m0 = blockIdx.x * 128;
    const int t2 = blockIdx.y;
    const float* B = g_phi + (size_t)t2 * 256 * ESZ;
    const int lr = tid >> 1, ls = (tid & 1) * 8;
    const int tx = tid & 15, ty = tid >> 4;

    ull acc[8][8];
#pragma unroll
    for (int i = 0; i < 8; i++)
#pragma unroll
        for (int j = 0; j < 8; j++) acc[i][j] = 0ull;

    const float* Ap = W_ih + (size_t)(m0 + lr) * ESZ + ls;
    const float* Bp = B + (size_t)tid * ESZ;

    float4 a0 = *(const float4*)(Ap);
    float4 a1 = *(const float4*)(Ap + 4);
    float4 b0 = *(const float4*)(Bp);
    float4 b1 = *(const float4*)(Bp + 4);
    float4 b2 = *(const float4*)(Bp + 8);
    float4 b3 = *(const float4*)(Bp + 12);

    for (int kt = 0; kt < ESZ; kt += 16) {
        __syncthreads();
        As[ls + 0][lr] = a0.x; As[ls + 1][lr] = a0.y; As[ls + 2][lr] = a0.z; As[ls + 3][lr] = a0.w;
        As[ls + 4][lr] = a1.x; As[ls + 5][lr] = a1.y; As[ls + 6][lr] = a1.z; As[ls + 7][lr] = a1.w;
        Bs[0][tid] = b0.x;  Bs[1][tid] = b0.y;  Bs[2][tid] = b0.z;  Bs[3][tid] = b0.w;
        Bs[4][tid] = b1.x;  Bs[5][tid] = b1.y;  Bs[6][tid] = b1.z;  Bs[7][tid] = b1.w;
        Bs[8][tid] = b2.x;  Bs[9][tid] = b2.y;  Bs[10][tid] = b2.z; Bs[11][tid] = b2.w;
        Bs[12][tid] = b3.x; Bs[13][tid] = b3.y; Bs[14][tid] = b3.z; Bs[15][tid] = b3.w;
        __syncthreads();
        if (kt + 16 < ESZ) {           // prefetch next tile (hidden under compute)
            a0 = *(const float4*)(Ap + kt + 16);
            a1 = *(const float4*)(Ap + kt + 20);
            b0 = *(const float4*)(Bp + kt + 16);
            b1 = *(const float4*)(Bp + kt + 20);
            b2 = *(const float4*)(Bp + kt + 24);
            b3 = *(const float4*)(Bp + kt + 28);
        }
#pragma unroll
        for (int k = 0; k < 16; k++) {
            float4 av0 = *(const float4*)&As[k][ty * 8];
            float4 av1 = *(const float4*)&As[k][ty * 8 + 4];
            float4 bv0 = *(const float4*)&Bs[k][tx * 4];
            float4 bv1 = *(const float4*)&Bs[k][tx * 4 + 64];
            float4 bv2 = *(const float4*)&Bs[k][tx * 4 + 128];
            float4 bv3 = *(const float4*)&Bs[k][tx * 4 + 192];
            ull bp[8] = {pk2(bv0.x, bv0.y), pk2(bv0.z, bv0.w),
                         pk2(bv1.x, bv1.y), pk2(bv1.z, bv1.w),
                         pk2(bv2.x, bv2.y), pk2(bv2.z, bv2.w),
                         pk2(bv3.x, bv3.y), pk2(bv3.z, bv3.w)};
            float aa[8] = {av0.x, av0.y, av0.z, av0.w, av1.x, av1.y, av1.z, av1.w};
#pragma unroll
            for (int i = 0; i < 8; i++) {
                ull ap = pk2(aa[i], aa[i]);
#pragma unroll
                for (int j = 0; j < 8; j++)
                    acc[i][j] = fma2(ap, bp[j], acc[i][j]);
            }
        }
    }
#pragma unroll
    for (int i = 0; i < 8; i++) {
        int row = m0 + ty * 8 + i;
        float brow = __ldg(b_ih + row);
#pragma unroll
        for (int jj = 0; jj < 4; jj++) {
            int nn = tx * 4 + jj * 64;
            int tt = 2 * t2 + (nn >> 7);
            int ib = nn & 127;
            float2 v0 = up2(acc[i][2 * jj]);
            float2 v1 = up2(acc[i][2 * jj + 1]);
            *(float4*)(g_xg + (size_t)tt * G3 * BSZ + (size_t)row * BSZ + ib) =
                make_float4(v0.x + brow, v0.y + brow, v1.x + brow, v1.y + brow);
        }
    }
}

// ---------------- K4a v15: he = relu(hs @ W_he^T + b_he), A read from g_hsT ----------------
// Block x = one t. A-tile loads hsT[t][k][i] coalesced along i.
__global__ void __launch_bounds__(256) k4a_he(const float* __restrict__ W_he,
                                              const float* __restrict__ b_he) {
    __shared__ float As[16][128];
    __shared__ float Bs[16][128];
    const int tid = threadIdx.x;
    const int t = blockIdx.x;
    const int m0 = t * 128, n0 = 0;
    const float* hsrc = g_hsT + (size_t)t * HS_SLICE;
    const int lr = tid >> 1, ls = (tid & 1) * 8;
    const int tx = tid & 15, ty = tid >> 4;
    const int kkA = tid >> 4;            // 0..15
    const int ioA = (tid & 15) * 8;      // 0..120
    ull acc[8][4];
#pragma unroll
    for (int i = 0; i < 8; i++)
#pragma unroll
        for (int j = 0; j < 4; j++) acc[i][j] = 0ull;

    const float* Bp = W_he + (size_t)(n0 + lr) * HSZ + ls;

    for (int kt = 0; kt < HSZ; kt += 16) {
        const float* ap = hsrc + (size_t)(kt + kkA) * BSZ + ioA;
        float4 a0 = *(const float4*)(ap);
        float4 a1 = *(const float4*)(ap + 4);
        float4 b0 = *(const float4*)(Bp + kt);
        float4 b1 = *(const float4*)(Bp + kt + 4);
        __syncthreads();
        *(float4*)&As[kkA][ioA]     = a0;
        *(float4*)&As[kkA][ioA + 4] = a1;
        Bs[ls + 0][lr] = b0.x; Bs[ls + 1][lr] = b0.y; Bs[ls + 2][lr] = b0.z; Bs[ls + 3][lr] = b0.w;
        Bs[ls + 4][lr] = b1.x; Bs[ls + 5][lr] = b1.y; Bs[ls + 6][lr] = b1.z; Bs[ls + 7][lr] = b1.w;
        __syncthreads();
#pragma unroll
        for (int k = 0; k < 16; k++) {
            float4 av0 = *(const float4*)&As[k][ty * 8];
            float4 av1 = *(const float4*)&As[k][ty * 8 + 4];
            float4 bv0 = *(const float4*)&Bs[k][tx * 8];
            float4 bv1 = *(const float4*)&Bs[k][tx * 8 + 4];
            ull bp0 = pk2(bv0.x, bv0.y), bp1 = pk2(bv0.z, bv0.w);
            ull bp2 = pk2(bv1.x, bv1.y), bp3 = pk2(bv1.z, bv1.w);
            float aa[8] = {av0.x, av0.y, av0.z, av0.w, av1.x, av1.y, av1.z, av1.w};
#pragma unroll
            for (int i = 0; i < 8; i++) {
                ull ap2 = pk2(aa[i], aa[i]);
                acc[i][0] = fma2(ap2, bp0, acc[i][0]);
                acc[i][1] = fma2(ap2, bp1, acc[i][1]);
                acc[i][2] = fma2(ap2, bp2, acc[i][2]);
                acc[i][3] = fma2(ap2, bp3, acc[i][3]);
            }
        }
    }
    float bvals[8];
#pragma unroll
    for (int j = 0; j < 8; j++) bvals[j] = __ldg(b_he + n0 + tx * 8 + j);
#pragma unroll
    for (int i = 0; i < 8; i++) {
        int row = m0 + ty * 8 + i;
        float out[8]; float2 v;
        v = up2(acc[i][0]); out[0] = v.x; out[1] = v.y;
        v = up2(acc[i][1]); out[2] = v.x; out[3] = v.y;
        v = up2(acc[i][2]); out[4] = v.x; out[5] = v.y;
        v = up2(acc[i][3]); out[6] = v.x; out[7] = v.y;
#pragma unroll
        for (int j = 0; j < 8; j++) out[j] = fmaxf(out[j] + bvals[j], 0.f);
        float4* dst = (float4*)(g_he + (size_t)row * SSZ + n0 + tx * 8);
        dst[0] = make_float4(out[0], out[1], out[2], out[3]);
        dst[1] = make_float4(out[4], out[5], out[6], out[7]);
    }
}

// ---------------- K3: persistent GRU v15 (= v14 minus g_hs stores) ----------------
__global__ void __launch_bounds__(512, 2) k3_gru(const float* __restrict__ W_hh,
                                                 const float* __restrict__ b_hh) {
    extern __shared__ __align__(16) ull smemBuf[];
    ull* sW = smemBuf;
    ull* sP = smemBuf + SW_ULL;

    const int tid = threadIdx.x;
    const int bg = blockIdx.x;
    const int ug = blockIdx.y;
    const int ubase = ug * 8;
    const int ibase = bg * 32;
    unsigned* my_ctr = &g_arrive4[bg * 32];

    for (int e = tid; e < 512 * 4 * 3; e += 512) {
        int g = e % 3;
        int up_ = (e / 3) & 3;
        int k = e / 12;
        int j0 = ubase + 2 * up_;
        float w0 = W_hh[(size_t)(g * HSZ + j0) * HSZ + k];
        float w1 = W_hh[(size_t)(g * HSZ + j0 + 1) * HSZ + k];
        sW[(size_t)(k * 4 + up_) * 4 + g] = pk2(w0, w1);
    }

    const int iq = tid & 7;
    const int up = (tid >> 3) & 3;
    const int kq = tid >> 5;

    // conflict-free epilogue identity (v14)
    const int iqB = tid & 7;
    const int upB = (tid >> 3) & 3;
    const int rB  = (tid >> 5) & 3;
    const int iB  = ibase + 4 * iqB + rB;
    const int jB  = ubase + 2 * upB;
    float bR0 = 0.f, bR1 = 0.f, bZ0 = 0.f, bZ1 = 0.f, bN0 = 0.f, bN1 = 0.f;
    if (tid < 128) {
        bR0 = __ldg(b_hh + jB);            bR1 = __ldg(b_hh + jB + 1);
        bZ0 = __ldg(b_hh + HSZ + jB);      bZ1 = __ldg(b_hh + HSZ + jB + 1);
        const float* xb0 = g_xg + iB;
        pf_l2(xb0 + (size_t)(0 * HSZ + jB) * BSZ);
        pf_l2(xb0 + (size_t)(1 * HSZ + jB) * BSZ);
        pf_l2(xb0 + (size_t)(2 * HSZ + jB) * BSZ);
        bN0 = __ldg(b_hh + 2 * HSZ + jB);  bN1 = __ldg(b_hh + 2 * HSZ + jB + 1);
    }
    __syncthreads();

    for (int t = 0; t < NSTEP; t++) {
        const float* hT  = g_hsT + (size_t)t * HS_SLICE;
        float*       hTn = g_hsT + (size_t)(t + 1) * HS_SLICE;

        if (tid < 128 && t + 1 < NSTEP) {
            const float* xb = g_xg + (size_t)(t + 1) * G3 * BSZ + iB;
            pf_l2(xb + (size_t)(0 * HSZ + jB) * BSZ);
            pf_l2(xb + (size_t)(0 * HSZ + jB + 1) * BSZ);
            pf_l2(xb + (size_t)(1 * HSZ + jB) * BSZ);
            pf_l2(xb + (size_t)(1 * HSZ + jB + 1) * BSZ);
            pf_l2(xb + (size_t)(2 * HSZ + jB) * BSZ);
            pf_l2(xb + (size_t)(2 * HSZ + jB + 1) * BSZ);
        }

        ull acc[3][4];
#pragma unroll
        for (int g = 0; g < 3; g++)
#pragma unroll
            for (int r = 0; r < 4; r++) acc[g][r] = 0ull;

        const float4* hb = (const float4*)hT + (size_t)(kq * 32) * 32 + bg * 8 + iq;
        const ull*    wb = sW + (size_t)(kq * 32) * 16 + up * 4;

#pragma unroll 4
        for (int c = 0; c < 32; c++) {
            float4 h = __ldg(hb + (size_t)c * 32);
            ull p0 = pk2(h.x, h.x), p1 = pk2(h.y, h.y);
            ull p2 = pk2(h.z, h.z), p3 = pk2(h.w, h.w);
            const ull* wp = wb + (size_t)c * 16;
            ulonglong2 wab = *(const ulonglong2*)wp;
            ull wc = wp[2];
            acc[0][0] = fma2(p0, wab.x, acc[0][0]);
            acc[0][1] = fma2(p1, wab.x, acc[0][1]);
            acc[0][2] = fma2(p2, wab.x, acc[0][2]);
            acc[0][3] = fma2(p3, wab.x, acc[0][3]);
            acc[1][0] = fma2(p0, wab.y, acc[1][0]);
            acc[1][1] = fma2(p1, wab.y, acc[1][1]);
            acc[1][2] = fma2(p2, wab.y, acc[1][2]);
            acc[1][3] = fma2(p3, wab.y, acc[1][3]);
            acc[2][0] = fma2(p0, wc, acc[2][0]);
            acc[2][1] = fma2(p1, wc, acc[2][1]);
            acc[2][2] = fma2(p2, wc, acc[2][2]);
            acc[2][3] = fma2(p3, wc, acc[2][3]);
        }
#pragma unroll
        for (int g = 0; g < 3; g++)
#pragma unroll
            for (int r = 0; r < 4; r++)
                sP[(size_t)((kq * 3 + g) * 4 + r) * 32 + up * 8 + iq] = acc[g][r];
        __syncthreads();

        if (tid < 128) {
            const float* xb = g_xg + (size_t)t * G3 * BSZ + iB;
            float xr0 = __ldg(xb + (size_t)(0 * HSZ + jB) * BSZ);
            float xr1 = __ldg(xb + (size_t)(0 * HSZ + jB + 1) * BSZ);
            float xz0 = __ldg(xb + (size_t)(1 * HSZ + jB) * BSZ);
            float xz1 = __ldg(xb + (size_t)(1 * HSZ + jB + 1) * BSZ);
            float xn0 = __ldg(xb + (size_t)(2 * HSZ + jB) * BSZ);
            float xn1 = __ldg(xb + (size_t)(2 * HSZ + jB + 1) * BSZ);
            float hp0 = __ldg(hT + (size_t)jB * BSZ + iB);
            float hp1 = __ldg(hT + (size_t)(jB + 1) * BSZ + iB);

            ull sr = 0ull, sz = 0ull, sn = 0ull;
            const ull* pb = sP + (size_t)rB * 32 + upB * 8 + iqB;
#pragma unroll 4
            for (int q = 0; q < 16; q++) {
                const ull* pq = pb + (size_t)q * 384;
                sr = add2(sr, pq[0]);
                sz = add2(sz, pq[128]);
                sn = add2(sn, pq[256]);
            }
            float2 hr = up2(sr), hz = up2(sz), hn = up2(sn);

            float r0 = sigm(xr0 + hr.x + bR0);
            float z0 = sigm(xz0 + hz.x + bZ0);
            float n0 = tanhf(xn0 + r0 * (hn.x + bN0));
            float o0 = (1.f - z0) * n0 + z0 * hp0;

            float r1 = sigm(xr1 + hr.y + bR1);
            float z1 = sigm(xz1 + hz.y + bZ1);
            float n1 = tanhf(xn1 + r1 * (hn.y + bN1));
            float o1 = (1.f - z1) * n1 + z1 * hp1;

            hTn[(size_t)jB * BSZ + iB]       = o0;
            hTn[(size_t)(jB + 1) * BSZ + iB] = o1;
        }
        __threadfence();
        __syncthreads();
        if (tid == 0) {
            atomicAdd(my_ctr, 1u);
            unsigned target = 64u * (unsigned)(t + 1);
            while (*(volatile unsigned*)my_ctr < target) { __nanosleep(32); }
            __threadfence();
        }
        __syncthreads();
    }
}

// ---------------- K4b: per-event loss ----------------
__global__ void __launch_bounds__(256) k4b_loss(const float* __restrict__ x,
                                                const float* __restrict__ tin,
                                                const float* __restrict__ maskp,
                                                const float* __restrict__ W_mu,
                                                const float* __restrict__ b_mu,
                                                const float* __restrict__ W_lv,
                                                const float* __restrict__ b_lv,
                                                const float* __restrict__ h_infl,
                                                const float* __restrict__ ti_p,
                                                const float* __restrict__ bi_p) {
    __shared__ float s_he[8][SSZ];
    __shared__ float s_red[8];
    const int tid = threadIdx.x;
    const int w = tid >> 5, lane = tid & 31;
    const int q = blockIdx.x * 8 + w;
    const int t = (q >> 7) + 1;
    const int i = q & 127;
    const size_t row = (size_t)t * BSZ + i;

    ((float4*)s_he[w])[lane] = ((const float4*)(g_he + row * SSZ))[lane];
    __syncwarp();

    float p = 0.f;
#pragma unroll
    for (int kk = 0; kk < 4; kk++) {
        int k = lane + 32 * kk;
        p += s_he[w][k] * __ldg(h_infl + k);
    }
#pragma unroll
    for (int off = 16; off; off >>= 1) p += __shfl_xor_sync(0xffffffffu, p, off);

    float marker = 0.f;
    if (lane < MDIM) {
        float accm = __ldg(b_mu + lane);
        float accl = __ldg(b_lv + lane);
        const float4* wm = (const float4*)(W_mu + lane * SSZ);
        const float4* wl = (const float4*)(W_lv + lane * SSZ);
#pragma unroll 8
        for (int kk = 0; kk < 32; kk++) {
            float4 hev = ((const float4*)s_he[w])[kk];
            float4 a = __ldg(wm + kk);
            float4 b = __ldg(wl + kk);
            accm += hev.x * a.x + hev.y * a.y + hev.z * a.z + hev.w * a.w;
            accl += hev.x * b.x + hev.y * b.y + hev.z * b.z + hev.w * b.w;
        }
        float xv = __ldg(x + row * MDIM + lane);
        float sig = fmaxf(expf(0.5f * accl), 0.01f);
        float d = (xv - accm) / sig;
        marker = -0.5f * d * d - logf(sig) - 0.5f * LOG2PI;
    }
#pragma unroll
    for (int off = 16; off; off >>= 1) marker += __shfl_xor_sync(0xffffffffu, marker, off);

    if (lane == 0) {
        float ti = __ldg(ti_p);
        float bi = __ldg(bi_p);
        float dt = __ldg(tin + row * 2 + 1);
        float term1 = p + ti * dt + bi;
        float time_ll = term1 + (expf(p + bi) - expf(term1)) / ti;
        float m = __ldg(maskp + row);
        s_red[w] = (-time_ll - marker) * m;
    }
    __syncthreads();
    if (tid == 0) {
        float s = 0.f;
#pragma unroll
        for (int k = 0; k < 8; k++) s += s_red[k];
        g_partial[blockIdx.x] = s;
    }
}

// ---------------- K5: deterministic final reduce ----------------
__global__ void __launch_bounds__(256) k5_reduce(float* __restrict__ out) {
    __shared__ float s[256];
    const int tid = threadIdx.x;
    float a = 0.f;
    for (int idx = tid; idx < NB4B; idx += 256) a += g_partial[idx];
    s[tid] = a;
    __syncthreads();
    for (int off = 128; off; off >>= 1) {
        if (tid < off) s[tid] += s[tid + off];
        __syncthreads();
    }
    if (tid == 0) out[0] = s[0];
}

// ---------------- launch ----------------
extern "C" void kernel_launch(void* const* d_in, const int* in_sizes, int n_in,
                              void* d_out, int out_size) {
    const float* x       = (const float*)d_in[0];
    const float* tin     = (const float*)d_in[1];
    const float* maskp   = (const float*)d_in[2];
    const float* W_embed = (const float*)d_in[3];
    const float* b_embed = (const float*)d_in[4];
    const float* W_ih    = (const float*)d_in[5];
    const float* b_ih    = (const float*)d_in[6];
    const float* W_hh    = (const float*)d_in[7];
    const float* b_hh    = (const float*)d_in[8];
    const float* W_he    = (const float*)d_in[9];
    const float* b_he    = (const float*)d_in[10];
    const float* W_mu    = (const float*)d_in[11];
    const float* b_mu    = (const float*)d_in[12];
    const float* W_lv    = (const float*)d_in[13];
    const float* b_lv    = (const float*)d_in[14];
    const float* h_infl  = (const float*)d_in[15];
    const float* ti_p    = (const float*)d_in[16];
    const float* bi_p    = (const float*)d_in[17];
    float* out = (float*)d_out;

    static bool attr_set = false;
    if (!attr_set) {
        cudaFuncSetAttribute(k3_gru, cudaFuncAttributeMaxDynamicSharedMemorySize, K3_SMEM_BYTES);
        attr_set = true;
    }

    k0_init<<<256, 256>>>();
    k1_embed<<<1024, 256>>>(x, W_embed, b_embed);
    k2_gatesT<<<dim3(12, 256), 256>>>(W_ih, b_ih);
    k3_gru<<<dim3(4, 64), 512, K3_SMEM_BYTES>>>(W_hh, b_hh);
    k4a_he<<<512, 256>>>(W_he, b_he);
    k4b_loss<<<NB4B, 256>>>(x, tin, maskp, W_mu, b_mu, W_lv, b_lv, h_infl, ti_p, bi_p);
    k5_reduce<<<1, 256>>>(out);
}